// round 2
// baseline (speedup 1.0000x reference)
#include <cuda_runtime.h>
#include <math_constants.h>

// Causal attention head: out = softmax(causal(Q K^T / sqrt(D))) V
// B=4, L=4096, D=128, fp32. Flash-attention-2 style SIMT tiling.
//
// Tiling: Br=Bc=64, 256 threads (16x16). Thread (ty,tx):
//   S fragment: rows 4ty..4ty+3, cols 4tx..4tx+3   (4x4)
//   O fragment: rows 4ty..4ty+3, cols 8tx..8tx+7   (4x8)
// Q,K stored transposed in smem ([D][64]) -> conflict-free float4 loads in S loop.
// Row-softmax stats reduced across the 16-thread row group (half warp) via shfl,
// so alpha / l live in registers for the O update (same ty -> same rows).

namespace {
constexpr int Bq = 64;
constexpr int Bk = 64;
constexpr int HD = 128;
constexpr int SEQ = 4096;
constexpr int NB = 4;
constexpr int NTHREADS = 256;
// Qt[128][64] + Kt[128][64] + Vs[64][128] + Ps[64][64]
constexpr int SMEM_FLOATS = HD * 64 + HD * 64 + 64 * HD + 64 * 64;  // 28672 -> 112KB
}  // namespace

__global__ __launch_bounds__(NTHREADS, 2)
void fa_fp32_kernel(const float* __restrict__ Kg_, const float* __restrict__ Qg_,
                    const float* __restrict__ Vg_, float* __restrict__ Og_) {
  extern __shared__ float sm[];
  float* Qt = sm;                // [HD][64] transposed
  float* Kt = Qt + HD * 64;      // [HD][64] transposed
  float* Vs = Kt + HD * 64;      // [64][HD] row-major
  float* Ps = Vs + 64 * HD;      // [64][64] row-major

  const int qt = blockIdx.x;
  const int b = blockIdx.y;
  const int q0 = qt * Bq;
  const int tid = threadIdx.x;
  const int tx = tid & 15;
  const int ty = tid >> 4;

  // ---- load Q tile transposed into Qt (once per block) ----
  {
    const float* Qg = Qg_ + ((size_t)b * SEQ + q0) * HD;
    const int r = tid >> 2;       // row 0..63
    const int c0 = tid & 3;       // float4 chunk phase
#pragma unroll
    for (int it = 0; it < 8; ++it) {
      const int c = (it << 2) + c0;  // float4 chunk 0..31 (d = 4c)
      const float4 v = reinterpret_cast<const float4*>(Qg + r * HD)[c];
      Qt[(4 * c + 0) * 64 + r] = v.x;
      Qt[(4 * c + 1) * 64 + r] = v.y;
      Qt[(4 * c + 2) * 64 + r] = v.z;
      Qt[(4 * c + 3) * 64 + r] = v.w;
    }
  }

  float o[4][8];
#pragma unroll
  for (int i = 0; i < 4; ++i)
#pragma unroll
    for (int j = 0; j < 8; ++j) o[i][j] = 0.f;

  float m_run[4], l_run[4];
#pragma unroll
  for (int i = 0; i < 4; ++i) {
    m_run[i] = -CUDART_INF_F;
    l_run[i] = 0.f;
  }

  const float scale = 0.088388347648318447f;  // 1/sqrt(128)

  for (int kt = 0; kt <= qt; ++kt) {
    const int k0 = kt * Bk;
    __syncthreads();  // protect Kt/Vs/Ps from previous iteration's readers

    // ---- load K tile transposed, V tile direct ----
    {
      const float* Kg = Kg_ + ((size_t)b * SEQ + k0) * HD;
      const int r = tid >> 2;
      const int c0 = tid & 3;
#pragma unroll
      for (int it = 0; it < 8; ++it) {
        const int c = (it << 2) + c0;
        const float4 v = reinterpret_cast<const float4*>(Kg + r * HD)[c];
        Kt[(4 * c + 0) * 64 + r] = v.x;
        Kt[(4 * c + 1) * 64 + r] = v.y;
        Kt[(4 * c + 2) * 64 + r] = v.z;
        Kt[(4 * c + 3) * 64 + r] = v.w;
      }
      const float4* Vg4 =
          reinterpret_cast<const float4*>(Vg_ + ((size_t)b * SEQ + k0) * HD);
      float4* Vs4 = reinterpret_cast<float4*>(Vs);
#pragma unroll
      for (int it = 0; it < 8; ++it) Vs4[tid + it * NTHREADS] = Vg4[tid + it * NTHREADS];
    }
    __syncthreads();

    // ---- S = Q K^T (4x4 fragment) ----
    float s[4][4];
#pragma unroll
    for (int i = 0; i < 4; ++i)
#pragma unroll
      for (int j = 0; j < 4; ++j) s[i][j] = 0.f;

    const float4* Qt4 = reinterpret_cast<const float4*>(Qt) + ty;
    const float4* Kt4 = reinterpret_cast<const float4*>(Kt) + tx;
#pragma unroll 8
    for (int d = 0; d < HD; ++d) {
      const float4 qv = Qt4[d * 16];
      const float4 kv = Kt4[d * 16];
      const float qa[4] = {qv.x, qv.y, qv.z, qv.w};
      const float ka[4] = {kv.x, kv.y, kv.z, kv.w};
#pragma unroll
      for (int i = 0; i < 4; ++i)
#pragma unroll
        for (int j = 0; j < 4; ++j) s[i][j] = fmaf(qa[i], ka[j], s[i][j]);
    }

    // ---- scale + causal mask (diagonal tile only) ----
    if (kt == qt) {
#pragma unroll
      for (int i = 0; i < 4; ++i)
#pragma unroll
        for (int j = 0; j < 4; ++j)
          s[i][j] = (4 * tx + j > 4 * ty + i) ? -CUDART_INF_F : s[i][j] * scale;
    } else {
#pragma unroll
      for (int i = 0; i < 4; ++i)
#pragma unroll
        for (int j = 0; j < 4; ++j) s[i][j] *= scale;
    }

    // ---- online softmax: row group = 16 threads (half warp, same ty) ----
    float alpha[4];
#pragma unroll
    for (int i = 0; i < 4; ++i) {
      float mx = fmaxf(fmaxf(s[i][0], s[i][1]), fmaxf(s[i][2], s[i][3]));
#pragma unroll
      for (int w = 8; w >= 1; w >>= 1)
        mx = fmaxf(mx, __shfl_xor_sync(0xffffffffu, mx, w));
      const float m_new = fmaxf(m_run[i], mx);
      alpha[i] = __expf(m_run[i] - m_new);  // first tile: exp(-inf)=0
      float rs = 0.f;
#pragma unroll
      for (int j = 0; j < 4; ++j) {
        s[i][j] = __expf(s[i][j] - m_new);  // masked: exp(-inf)=0
        rs += s[i][j];
      }
#pragma unroll
      for (int w = 8; w >= 1; w >>= 1) rs += __shfl_xor_sync(0xffffffffu, rs, w);
      l_run[i] = l_run[i] * alpha[i] + rs;
      m_run[i] = m_new;
    }

    // ---- store P fragment (contiguous float4 across tx: conflict-free) ----
#pragma unroll
    for (int i = 0; i < 4; ++i) {
      reinterpret_cast<float4*>(Ps)[(4 * ty + i) * 16 + tx] =
          make_float4(s[i][0], s[i][1], s[i][2], s[i][3]);
    }
    __syncthreads();

    // ---- O = O*alpha + P V (4x8 fragment) ----
#pragma unroll
    for (int i = 0; i < 4; ++i)
#pragma unroll
      for (int j = 0; j < 8; ++j) o[i][j] *= alpha[i];

    const float4* Vrd = reinterpret_cast<const float4*>(Vs) + tx * 2;
    const float* Prd = Ps + (4 * ty) * 64;
#pragma unroll 4
    for (int k = 0; k < Bk; ++k) {
      const float p[4] = {Prd[k], Prd[64 + k], Prd[128 + k], Prd[192 + k]};
      const float4 v0 = Vrd[k * 32];
      const float4 v1 = Vrd[k * 32 + 1];
      const float va[8] = {v0.x, v0.y, v0.z, v0.w, v1.x, v1.y, v1.z, v1.w};
#pragma unroll
      for (int i = 0; i < 4; ++i)
#pragma unroll
        for (int j = 0; j < 8; ++j) o[i][j] = fmaf(p[i], va[j], o[i][j]);
    }
  }

  // ---- normalize and write out ----
  float* Og = Og_ + ((size_t)b * SEQ + q0) * HD;
#pragma unroll
  for (int i = 0; i < 4; ++i) {
    const float inv = 1.f / l_run[i];
    float4 r0 = make_float4(o[i][0] * inv, o[i][1] * inv, o[i][2] * inv, o[i][3] * inv);
    float4 r1 = make_float4(o[i][4] * inv, o[i][5] * inv, o[i][6] * inv, o[i][7] * inv);
    float4* dst = reinterpret_cast<float4*>(Og + (4 * ty + i) * HD) + tx * 2;
    dst[0] = r0;
    dst[1] = r1;
  }
}

extern "C" void kernel_launch(void* const* d_in, const int* in_sizes, int n_in,
                              void* d_out, int out_size) {
  // metadata order matches setup_inputs dict: key, query, value
  const float* Kg = (const float*)d_in[0];
  const float* Qg = (const float*)d_in[1];
  const float* Vg = (const float*)d_in[2];
  float* Og = (float*)d_out;

  const int smem_bytes = SMEM_FLOATS * sizeof(float);  // 114688
  cudaFuncSetAttribute(fa_fp32_kernel, cudaFuncAttributeMaxDynamicSharedMemorySize,
                       smem_bytes);

  dim3 grid(SEQ / Bq, NB);
  fa_fp32_kernel<<<grid, NTHREADS, smem_bytes>>>(Kg, Qg, Vg, Og);
}

// round 4
// speedup vs baseline: 8.6591x; 8.6591x over previous
#include <cuda_runtime.h>
#include <cuda_bf16.h>
#include <math_constants.h>
#include <cstdint>

// Causal attention B=4 L=4096 D=128 fp32 via mma.sync bf16 hi/lo split (3-term).
// Pass 1: convert Q/K/V fp32 -> bf16 hi + bf16 lo (device-global scratch).
// Pass 2: FA2 with m16n8k16 HMMA; CTA p handles q-tiles p and 63-p (65 units each).

namespace {
constexpr int SEQ = 4096, HD = 128, NB = 4;
constexpr int BQ = 64, BK = 64;
constexpr int NQT = SEQ / BQ;  // 64
constexpr int NTH = 128;
constexpr size_t TELEM = (size_t)NB * SEQ * HD;  // 2097152 per tensor

// smem byte offsets (each tile 64x128 bf16 = 16KB, row stride 256B)
constexpr int SM_QH = 0, SM_QL = 16384, SM_KH = 32768, SM_KL = 49152,
              SM_VH = 65536, SM_VL = 81920, SMEM_BYTES = 98304;
}  // namespace

__device__ __nv_bfloat16 g_hi[3][TELEM];  // 0=K, 1=Q, 2=V
__device__ __nv_bfloat16 g_lo[3][TELEM];

namespace {

__device__ __forceinline__ unsigned smem_u32(const void* p) {
  unsigned a;
  asm("{ .reg .u64 t; cvta.to.shared.u64 t, %1; cvt.u32.u64 %0, t; }" : "=r"(a) : "l"(p));
  return a;
}

__device__ __forceinline__ void splitpk(float x, float y, unsigned& hi, unsigned& lo) {
  __nv_bfloat162 h = __floats2bfloat162_rn(x, y);
  hi = *reinterpret_cast<unsigned*>(&h);
  __nv_bfloat162 l = __floats2bfloat162_rn(x - __bfloat162float(h.x),
                                           y - __bfloat162float(h.y));
  lo = *reinterpret_cast<unsigned*>(&l);
}

__device__ __forceinline__ void ldsm4(unsigned* r, unsigned a) {
  asm volatile("ldmatrix.sync.aligned.m8n8.x4.shared.b16 {%0,%1,%2,%3}, [%4];"
               : "=r"(r[0]), "=r"(r[1]), "=r"(r[2]), "=r"(r[3]) : "r"(a));
}

__device__ __forceinline__ void ldsm4t(unsigned* r, unsigned a) {
  asm volatile("ldmatrix.sync.aligned.m8n8.x4.trans.shared.b16 {%0,%1,%2,%3}, [%4];"
               : "=r"(r[0]), "=r"(r[1]), "=r"(r[2]), "=r"(r[3]) : "r"(a));
}

__device__ __forceinline__ void mma16816(float* d, const unsigned* a, unsigned b0,
                                         unsigned b1) {
  asm volatile(
      "mma.sync.aligned.m16n8k16.row.col.f32.bf16.bf16.f32 "
      "{%0,%1,%2,%3}, {%4,%5,%6,%7}, {%8,%9}, {%0,%1,%2,%3};"
      : "+f"(d[0]), "+f"(d[1]), "+f"(d[2]), "+f"(d[3])
      : "r"(a[0]), "r"(a[1]), "r"(a[2]), "r"(a[3]), "r"(b0), "r"(b1));
}

// Copy a 64x128 bf16 row-major tile from global into swizzled smem.
// Chunk = 16B; smem addr = row*256 + ((chunk ^ (row&7)) << 4).
__device__ __forceinline__ void copy_tile(char* sm, int off, const __nv_bfloat16* g,
                                          int tid) {
  const uint4* g4 = (const uint4*)g;
#pragma unroll
  for (int it = 0; it < 8; ++it) {
    const int c16 = it * 128 + tid;  // 0..1023
    const int row = c16 >> 4, c = c16 & 15;
    const uint4 v = g4[c16];
    *(uint4*)(sm + off + row * 256 + ((c ^ (row & 7)) << 4)) = v;
  }
}
}  // namespace

// ---- Pass 1: fp32 -> bf16 hi/lo ----
__global__ void cvt_kernel(const float* __restrict__ K, const float* __restrict__ Q,
                           const float* __restrict__ V) {
  constexpr int N4 = (int)(TELEM / 4);
  const int stride = gridDim.x * blockDim.x;
  for (int idx = blockIdx.x * blockDim.x + threadIdx.x; idx < 3 * N4; idx += stride) {
    const int t = idx / N4, e = idx - t * N4;
    const float* src = (t == 0) ? K : ((t == 1) ? Q : V);
    const float4 v = ((const float4*)src)[e];
    unsigned h0, l0, h1, l1;
    splitpk(v.x, v.y, h0, l0);
    splitpk(v.z, v.w, h1, l1);
    ((uint2*)g_hi[t])[e] = make_uint2(h0, h1);
    ((uint2*)g_lo[t])[e] = make_uint2(l0, l1);
  }
}

// ---- Pass 2: flash attention ----
__global__ __launch_bounds__(NTH, 1)
void fa_mma_kernel(float* __restrict__ Og) {
  extern __shared__ char sm[];
  const unsigned smb = smem_u32(sm);
  const int tid = threadIdx.x, lane = tid & 31, w = tid >> 5;
  const int g = lane >> 3, l7 = lane & 7, quad = lane >> 2, qlane = lane & 3;
  const int pair = blockIdx.x, b = blockIdx.y;

  const __nv_bfloat16* Kh = g_hi[0] + (size_t)b * SEQ * HD;
  const __nv_bfloat16* Kl = g_lo[0] + (size_t)b * SEQ * HD;
  const __nv_bfloat16* Qh = g_hi[1] + (size_t)b * SEQ * HD;
  const __nv_bfloat16* Ql = g_lo[1] + (size_t)b * SEQ * HD;
  const __nv_bfloat16* Vh = g_hi[2] + (size_t)b * SEQ * HD;
  const __nv_bfloat16* Vl = g_lo[2] + (size_t)b * SEQ * HD;

  // ldmatrix per-lane row/chunk offsets (see fragment mapping derivation)
  const int rowAl = ((g & 1) << 3) + l7;        // A (Q): g1/g3 -> rows+8
  const int cAoff = g >> 1;                     //        g2/g3 -> k+8
  const int rowBl = (((g >> 1) & 1) << 3) + l7; // B (K): g2/g3 -> rows(n)+8
  const int cBoff = g & 1;                      //        g1/g3 -> k+8
  const int rowVl = ((g & 1) << 3) + l7;        // V(trans): g1/g3 -> keys+8
  const int cVoff = g >> 1;                     //        g2/g3 -> d+8

  const float scale = 0.088388347648318447f;  // 1/sqrt(128)

  for (int half = 0; half < 2; ++half) {
    const int qt = half ? (NQT - 1 - pair) : pair;
    const int q0 = qt * BQ;

    __syncthreads();  // previous half's readers done before Q overwrite
    copy_tile(sm, SM_QH, Qh + (size_t)q0 * HD, tid);
    copy_tile(sm, SM_QL, Ql + (size_t)q0 * HD, tid);

    float o[16][4];
#pragma unroll
    for (int n = 0; n < 16; ++n)
#pragma unroll
      for (int e = 0; e < 4; ++e) o[n][e] = 0.f;
    float m0 = -CUDART_INF_F, m1 = -CUDART_INF_F, l0 = 0.f, l1 = 0.f;

    for (int kt = 0; kt <= qt; ++kt) {
      __syncthreads();  // previous iteration's readers done
      const int k0 = kt * BK;
      copy_tile(sm, SM_KH, Kh + (size_t)k0 * HD, tid);
      copy_tile(sm, SM_KL, Kl + (size_t)k0 * HD, tid);
      copy_tile(sm, SM_VH, Vh + (size_t)k0 * HD, tid);
      copy_tile(sm, SM_VL, Vl + (size_t)k0 * HD, tid);
      __syncthreads();

      // ---- S = Qh*Kh + Qh*Kl + Ql*Kh ----
      float s[8][4];
#pragma unroll
      for (int n = 0; n < 8; ++n)
#pragma unroll
        for (int e = 0; e < 4; ++e) s[n][e] = 0.f;

      const unsigned arow = smb + SM_QH + (unsigned)(16 * w + rowAl) * 256u;
#pragma unroll
      for (int ks = 0; ks < 8; ++ks) {
        unsigned ah[4], al[4];
        const unsigned ca = (unsigned)(((2 * ks + cAoff) ^ l7) << 4);
        ldsm4(ah, arow + ca);
        ldsm4(al, arow + 16384u + ca);
        const unsigned cb = (unsigned)(((2 * ks + cBoff) ^ l7) << 4);
#pragma unroll
        for (int t = 0; t < 4; ++t) {
          unsigned bh[4], bl[4];
          const unsigned kaddr = smb + SM_KH + (unsigned)(t * 16 + rowBl) * 256u + cb;
          ldsm4(bh, kaddr);
          ldsm4(bl, kaddr + 16384u);
          mma16816(s[2 * t], ah, bh[0], bh[1]);
          mma16816(s[2 * t], ah, bl[0], bl[1]);
          mma16816(s[2 * t], al, bh[0], bh[1]);
          mma16816(s[2 * t + 1], ah, bh[2], bh[3]);
          mma16816(s[2 * t + 1], ah, bl[2], bl[3]);
          mma16816(s[2 * t + 1], al, bh[2], bh[3]);
        }
      }

      // ---- scale + causal mask ----
#pragma unroll
      for (int n = 0; n < 8; ++n)
#pragma unroll
        for (int e = 0; e < 4; ++e) s[n][e] *= scale;
      if (kt == qt) {
        const int r0l = 16 * w + quad;
#pragma unroll
        for (int n = 0; n < 8; ++n) {
          const int c0 = 8 * n + 2 * qlane;
          if (c0 > r0l) s[n][0] = -CUDART_INF_F;
          if (c0 + 1 > r0l) s[n][1] = -CUDART_INF_F;
          if (c0 > r0l + 8) s[n][2] = -CUDART_INF_F;
          if (c0 + 1 > r0l + 8) s[n][3] = -CUDART_INF_F;
        }
      }

      // ---- online softmax (quad = the 4 lanes sharing a row) ----
      float mx0 = -CUDART_INF_F, mx1 = -CUDART_INF_F;
#pragma unroll
      for (int n = 0; n < 8; ++n) {
        mx0 = fmaxf(mx0, fmaxf(s[n][0], s[n][1]));
        mx1 = fmaxf(mx1, fmaxf(s[n][2], s[n][3]));
      }
      mx0 = fmaxf(mx0, __shfl_xor_sync(0xffffffffu, mx0, 1));
      mx0 = fmaxf(mx0, __shfl_xor_sync(0xffffffffu, mx0, 2));
      mx1 = fmaxf(mx1, __shfl_xor_sync(0xffffffffu, mx1, 1));
      mx1 = fmaxf(mx1, __shfl_xor_sync(0xffffffffu, mx1, 2));
      const float m0n = fmaxf(m0, mx0), m1n = fmaxf(m1, mx1);
      const float a0 = __expf(m0 - m0n), a1 = __expf(m1 - m1n);
      float s0 = 0.f, s1 = 0.f;
#pragma unroll
      for (int n = 0; n < 8; ++n) {
        s[n][0] = __expf(s[n][0] - m0n);
        s[n][1] = __expf(s[n][1] - m0n);
        s[n][2] = __expf(s[n][2] - m1n);
        s[n][3] = __expf(s[n][3] - m1n);
        s0 += s[n][0] + s[n][1];
        s1 += s[n][2] + s[n][3];
      }
      s0 += __shfl_xor_sync(0xffffffffu, s0, 1);
      s0 += __shfl_xor_sync(0xffffffffu, s0, 2);
      s1 += __shfl_xor_sync(0xffffffffu, s1, 1);
      s1 += __shfl_xor_sync(0xffffffffu, s1, 2);
      l0 = l0 * a0 + s0;
      l1 = l1 * a1 + s1;
      m0 = m0n;
      m1 = m1n;

#pragma unroll
      for (int n = 0; n < 16; ++n) {
        o[n][0] *= a0;
        o[n][1] *= a0;
        o[n][2] *= a1;
        o[n][3] *= a1;
      }

      // ---- O += Ph*Vh + Ph*Vl + Pl*Vh ----
#pragma unroll
      for (int ks = 0; ks < 4; ++ks) {
        unsigned ah[4], al[4];
        splitpk(s[2 * ks][0], s[2 * ks][1], ah[0], al[0]);
        splitpk(s[2 * ks][2], s[2 * ks][3], ah[1], al[1]);
        splitpk(s[2 * ks + 1][0], s[2 * ks + 1][1], ah[2], al[2]);
        splitpk(s[2 * ks + 1][2], s[2 * ks + 1][3], ah[3], al[3]);
#pragma unroll
        for (int u = 0; u < 8; ++u) {
          unsigned vh[4], vl[4];
          const unsigned vaddr = smb + SM_VH + (unsigned)(16 * ks + rowVl) * 256u +
                                 (unsigned)(((2 * u + cVoff) ^ l7) << 4);
          ldsm4t(vh, vaddr);
          ldsm4t(vl, vaddr + 16384u);
          mma16816(o[2 * u], ah, vh[0], vh[1]);
          mma16816(o[2 * u], ah, vl[0], vl[1]);
          mma16816(o[2 * u], al, vh[0], vh[1]);
          mma16816(o[2 * u + 1], ah, vh[2], vh[3]);
          mma16816(o[2 * u + 1], ah, vl[2], vl[3]);
          mma16816(o[2 * u + 1], al, vh[2], vh[3]);
        }
      }
    }  // kt

    // ---- epilogue ----
    const float i0 = 1.f / l0, i1 = 1.f / l1;
    const int r0 = q0 + 16 * w + quad;
    float* og = Og + ((size_t)b * SEQ + r0) * HD;
#pragma unroll
    for (int n = 0; n < 16; ++n) {
      const int col = 8 * n + 2 * qlane;
      *(float2*)(og + col) = make_float2(o[n][0] * i0, o[n][1] * i0);
      *(float2*)(og + 8 * HD + col) = make_float2(o[n][2] * i1, o[n][3] * i1);
    }
  }  // half
}

extern "C" void kernel_launch(void* const* d_in, const int* in_sizes, int n_in,
                              void* d_out, int out_size) {
  const float* K = (const float*)d_in[0];
  const float* Q = (const float*)d_in[1];
  const float* V = (const float*)d_in[2];
  float* O = (float*)d_out;

  cvt_kernel<<<2048, 256>>>(K, Q, V);

  cudaFuncSetAttribute(fa_mma_kernel, cudaFuncAttributeMaxDynamicSharedMemorySize,
                       SMEM_BYTES);
  dim3 grid(NQT / 2, NB);
  fa_mma_kernel<<<grid, NTH, SMEM_BYTES>>>(O);
}